// round 13
// baseline (speedup 1.0000x reference)
#include <cuda_runtime.h>
#include <cuda_bf16.h>
#include <cstddef>

// Problem constants
#define B_  4
#define C_  256
#define H_  64
#define W_  64
#define P_  (H_*W_)       // 4096
#define COMP_ 64
#define S2_ 4
#define K2_ 25
#define EPS_ 1e-5f
#define MPAD_ 28          // mask gmem row padded to 28 floats (16B aligned)

typedef unsigned long long ull;

// ---- packed fp32x2 helpers (Blackwell FFMA2; IEEE fp32 per lane) ----------
__device__ __forceinline__ ull pk2(float lo, float hi) {
    ull r; asm("mov.b64 %0, {%1, %2};" : "=l"(r) : "f"(lo), "f"(hi)); return r;
}
__device__ __forceinline__ void upk2(ull v, float& lo, float& hi) {
    asm("mov.b64 {%0, %1}, %2;" : "=f"(lo), "=f"(hi) : "l"(v));
}
__device__ __forceinline__ ull fma2(ull a, ull b, ull c) {
    ull d; asm("fma.rn.f32x2 %0, %1, %2, %3;" : "=l"(d) : "l"(a), "l"(b), "l"(c));
    return d;
}
__device__ __forceinline__ ull add2(ull a, ull b) {
    ull d; asm("add.rn.f32x2 %0, %1, %2;" : "=l"(d) : "l"(a), "l"(b));
    return d;
}

// Scratch (device globals; no allocation)
__device__ float g_act[B_ * COMP_ * P_];                    // 4.19 MB
__device__ float g_part[4][B_ * S2_ * P_ * MPAD_];          // 4 x 7.34 MB partial logits
__device__ float g_mask2[B_ * S2_ * P_ * MPAD_];            // [b][s][p][28]  7.34 MB

// ---------------------------------------------------------------------------
// Kernel 1: 1x1 compression conv + BN(eval) + SiLU, split-K x2 + FFMA2. (R12)
// ---------------------------------------------------------------------------
__global__ __launch_bounds__(512) void k_compress(
    const float* __restrict__ x, const float* __restrict__ w_comp,
    const float* __restrict__ gamma, const float* __restrict__ beta,
    const float* __restrict__ mean, const float* __restrict__ var)
{
    __shared__ float ws[256][8];    // [c][o_local]
    __shared__ ull   red[256][4];   // team-1 partial sums (packed pairs)

    const int og = blockIdx.y;
    const int b  = blockIdx.z;
    const int tid = threadIdx.x;
    const int half = tid >> 8;      // c-team
    const int t = tid & 255;        // pixel within block
    const int p = (blockIdx.x << 8) + t;

    for (int i = tid; i < 256 * 8; i += 512) {
        int o = i & 7, c = i >> 3;
        ws[c][o] = w_comp[(og * 8 + o) * 256 + c];
    }
    __syncthreads();

    ull acc2[4];
#pragma unroll
    for (int j = 0; j < 4; j++) acc2[j] = 0ull;

    const float* xb = x + ((size_t)b * C_ + half * 128) * P_ + p;
    const int cbase = half * 128;
#pragma unroll 8
    for (int c = 0; c < 128; c++) {
        float xv = xb[(size_t)c * P_];
        ull xx = pk2(xv, xv);
        ulonglong2 wA = *(const ulonglong2*)&ws[cbase + c][0];
        ulonglong2 wB = *(const ulonglong2*)&ws[cbase + c][4];
        acc2[0] = fma2(wA.x, xx, acc2[0]);
        acc2[1] = fma2(wA.y, xx, acc2[1]);
        acc2[2] = fma2(wB.x, xx, acc2[2]);
        acc2[3] = fma2(wB.y, xx, acc2[3]);
    }

    if (half == 1) {
#pragma unroll
        for (int j = 0; j < 4; j++) red[t][j] = acc2[j];
    }
    __syncthreads();
    if (half == 0) {
        float acc[8];
#pragma unroll
        for (int j = 0; j < 4; j++) {
            ull s = add2(acc2[j], red[t][j]);
            upk2(s, acc[2 * j], acc[2 * j + 1]);
        }
#pragma unroll
        for (int o = 0; o < 8; o++) {
            int oc = og * 8 + o;
            float sc = gamma[oc] * rsqrtf(var[oc] + EPS_);
            float v = (acc[o] - mean[oc]) * sc + beta[oc];
            float a = v / (1.f + __expf(-v));          // SiLU
            g_act[((size_t)b * COMP_ + oc) * P_ + p] = a;
        }
    }
}

// ---------------------------------------------------------------------------
// Kernel 2: 3x3 encoder conv, ci-split x4, FFMA2 k-pairs -> partial logits. (R12)
// ---------------------------------------------------------------------------
#define ENC_ACT_F (16 * 18 * 18)   // 5184
#define ENC_W_F   (16 * 9 * 28)    // 4032

__global__ __launch_bounds__(256) void k_encoder(const float* __restrict__ w_enc)
{
    __shared__ float act_s[ENC_ACT_F];   // [cl][yy][xx] pitch 18, 16 ch
    __shared__ float w_s[ENC_W_F];       // [cl][q][28]

    const int s = blockIdx.y >> 2;
    const int quarter = blockIdx.y & 3;
    const int b = blockIdx.z;
    const int tile = blockIdx.x;
    const int ty0 = (tile >> 2) * 16, tx0 = (tile & 3) * 16;
    const int tid = threadIdx.x;
    const int ci0 = quarter * 16;

    for (int i = tid; i < ENC_W_F; i += 256) {
        int k = i % 28, cq = i / 28;
        int cl = cq / 9, q = cq % 9;
        float v = 0.f;
        if (k < 25) v = w_enc[(k * 4 + s) * 576 + (ci0 + cl) * 9 + q];
        w_s[i] = v;
    }
    for (int i = tid; i < ENC_ACT_F; i += 256) {
        int cl = i / 324, r = i % 324;
        int yy = r / 18, xx = r % 18;
        int gy = ty0 + yy - 1, gx = tx0 + xx - 1;
        float v = 0.f;
        if ((unsigned)gy < 64u && (unsigned)gx < 64u)
            v = g_act[((size_t)b * COMP_ + ci0 + cl) * P_ + gy * 64 + gx];
        act_s[i] = v;
    }
    __syncthreads();

    const int py = tid >> 4, px = tid & 15;
    ull acc2[13];
#pragma unroll
    for (int k = 0; k < 13; k++) acc2[k] = 0ull;

    for (int cl = 0; cl < 16; cl++) {
        float a[9];
        const float* ap = act_s + cl * 324 + py * 18 + px;
#pragma unroll
        for (int dy = 0; dy < 3; dy++)
#pragma unroll
            for (int dx = 0; dx < 3; dx++)
                a[dy * 3 + dx] = ap[dy * 18 + dx];

#pragma unroll
        for (int q = 0; q < 9; q++) {
            const ulonglong2* wq = (const ulonglong2*)(w_s + (cl * 9 + q) * 28);
            ull aa = pk2(a[q], a[q]);
            ulonglong2 w0 = wq[0], w1 = wq[1], w2 = wq[2];
            ulonglong2 w3 = wq[3], w4 = wq[4], w5 = wq[5];
            ull w6 = ((const ull*)(wq + 6))[0];
            acc2[0]  = fma2(w0.x, aa, acc2[0]);
            acc2[1]  = fma2(w0.y, aa, acc2[1]);
            acc2[2]  = fma2(w1.x, aa, acc2[2]);
            acc2[3]  = fma2(w1.y, aa, acc2[3]);
            acc2[4]  = fma2(w2.x, aa, acc2[4]);
            acc2[5]  = fma2(w2.y, aa, acc2[5]);
            acc2[6]  = fma2(w3.x, aa, acc2[6]);
            acc2[7]  = fma2(w3.y, aa, acc2[7]);
            acc2[8]  = fma2(w4.x, aa, acc2[8]);
            acc2[9]  = fma2(w4.y, aa, acc2[9]);
            acc2[10] = fma2(w5.x, aa, acc2[10]);
            acc2[11] = fma2(w5.y, aa, acc2[11]);
            acc2[12] = fma2(w6,   aa, acc2[12]);
        }
    }

    const int gp = (ty0 + py) * 64 + tx0 + px;
    ull* mp = (ull*)(g_part[quarter] + (((size_t)b * S2_ + s) * P_ + gp) * MPAD_);
#pragma unroll
    for (int k = 0; k < 13; k++) mp[k] = acc2[k];
    ((float*)mp)[26] = 0.f; ((float*)mp)[27] = 0.f;
}

// ---------------------------------------------------------------------------
// Kernel 2.5: combine 4 partials + softmax(25) -> g_mask2. (R12)
// ---------------------------------------------------------------------------
__global__ __launch_bounds__(256) void k_combine()
{
    __shared__ float sm[256 * MPAD_];
    const int tid = threadIdx.x;
    const size_t base = (size_t)blockIdx.x * 256 * MPAD_;

    const float4* p0 = (const float4*)(g_part[0] + base);
    const float4* p1 = (const float4*)(g_part[1] + base);
    const float4* p2 = (const float4*)(g_part[2] + base);
    const float4* p3 = (const float4*)(g_part[3] + base);
    float4* smv = (float4*)sm;
#pragma unroll
    for (int j = 0; j < 7; j++) {
        int i = j * 256 + tid;
        float4 a = p0[i], b = p1[i], c = p2[i], d = p3[i];
        smv[i] = make_float4(a.x + b.x + c.x + d.x, a.y + b.y + c.y + d.y,
                             a.z + b.z + c.z + d.z, a.w + b.w + c.w + d.w);
    }
    __syncthreads();

    float v[25];
#pragma unroll
    for (int k = 0; k < 25; k++) v[k] = sm[tid * MPAD_ + k];
    float m = v[0];
#pragma unroll
    for (int k = 1; k < 25; k++) m = fmaxf(m, v[k]);
    float sum = 0.f;
#pragma unroll
    for (int k = 0; k < 25; k++) { v[k] = __expf(v[k] - m); sum += v[k]; }
    float inv = 1.f / sum;

    float4* mp = (float4*)(g_mask2 + base + (size_t)tid * MPAD_);
    mp[0] = make_float4(v[0]*inv,  v[1]*inv,  v[2]*inv,  v[3]*inv);
    mp[1] = make_float4(v[4]*inv,  v[5]*inv,  v[6]*inv,  v[7]*inv);
    mp[2] = make_float4(v[8]*inv,  v[9]*inv,  v[10]*inv, v[11]*inv);
    mp[3] = make_float4(v[12]*inv, v[13]*inv, v[14]*inv, v[15]*inv);
    mp[4] = make_float4(v[16]*inv, v[17]*inv, v[18]*inv, v[19]*inv);
    mp[5] = make_float4(v[20]*inv, v[21]*inv, v[22]*inv, v[23]*inv);
    mp[6] = make_float4(v[24]*inv, 0.f, 0.f, 0.f);
}

// ---------------------------------------------------------------------------
// Kernel 3: reassembly + pixel shuffle, FFMA2 s-pairs — occupancy build.
// grid (64 tiles of 8x8, 32 cgroups of 8 ch, 4 b) = 8192 blocks.
// block 256 = 64 px * 4 csub (2 ch each). smem 42.4KB -> 5 blocks/SM.
// k-chunks of 5 keep mask regs at 20 -> target <=48 regs (5 blocks fit RF).
// ---------------------------------------------------------------------------
#define RA_XS_F  (8 * 480)                   // 3840
#define RA_MS_F  (64 * 108)                  // 6912
#define RA_SMEM_BYTES ((RA_XS_F + RA_MS_F) * 4)   // 43008

__global__ __launch_bounds__(256, 5) void k_reassemble(
    const float* __restrict__ x, float* __restrict__ out)
{
    extern __shared__ float rsm[];
    float* xs = rsm;                 // [cl][yy*40 + xx], 8 ch
    float* ms = rsm + RA_XS_F;       // [px*108 + k*4 + s]

    const int b = blockIdx.z;
    const int cg = blockIdx.y;       // 32 channel groups of 8
    const int tile = blockIdx.x;
    const int ty0 = (tile >> 3) * 8, tx0 = (tile & 7) * 8;
    const int tid = threadIdx.x;

    // x tile (halo 2, zero pad), pitched rows
    for (int i = tid; i < 8 * 144; i += 256) {
        int cl = i / 144, r = i % 144;
        int yy = r / 12, xx = r % 12;
        int gy = ty0 + yy - 2, gx = tx0 + xx - 2;
        float v = 0.f;
        if ((unsigned)gy < 64u && (unsigned)gx < 64u)
            v = x[(((size_t)b * C_ + cg * 8 + cl) * 64 + gy) * 64 + gx];
        xs[cl * 480 + yy * 40 + xx] = v;
    }
    // mask tile: transpose to [px][k][s] while loading (float4 gmem reads)
    for (int i = tid; i < 64 * 4 * 7; i += 256) {
        int px = i / 28, rem = i % 28;
        int s = rem / 7, j = rem % 7;
        int gp = (ty0 + (px >> 3)) * 64 + tx0 + (px & 7);
        float4 v = *((const float4*)(g_mask2 +
                     (((size_t)b * S2_ + s) * P_ + gp) * MPAD_) + j);
        float* dst = ms + px * 108 + s;
        int k = j * 4;
        dst[(k + 0) * 4] = v.x;
        if (k + 1 < 25) dst[(k + 1) * 4] = v.y;
        if (k + 2 < 25) dst[(k + 2) * 4] = v.z;
        if (k + 3 < 25) dst[(k + 3) * 4] = v.w;
    }
    __syncthreads();

    const int csub = tid >> 6;           // 2 channels each
    const int px   = tid & 63;
    const int py = px >> 3, pxl = px & 7;

    ull acc01[2], acc23[2];
#pragma unroll
    for (int ch = 0; ch < 2; ch++) { acc01[ch] = 0ull; acc23[ch] = 0ull; }

    const float* xbase = xs + csub * 2 * 480 + py * 40 + pxl;
    const ulonglong2* mrow = (const ulonglong2*)(ms + px * 108);

    // k-chunks of 5 (one dy row each) keep register pressure low
#pragma unroll
    for (int dy = 0; dy < 5; dy++) {
        const int kb = dy * 5;

        ull mk01[5], mk23[5];
#pragma unroll
        for (int j = 0; j < 5; j++) {
            ulonglong2 m = mrow[kb + j];
            mk01[j] = m.x; mk23[j] = m.y;
        }

#pragma unroll
        for (int ch = 0; ch < 2; ch++) {
            const float* xp = xbase + ch * 480 + dy * 40;
#pragma unroll
            for (int j = 0; j < 5; j++) {
                float xv = xp[j];
                ull xx = pk2(xv, xv);
                acc01[ch] = fma2(mk01[j], xx, acc01[ch]);
                acc23[ch] = fma2(mk23[j], xx, acc23[ch]);
            }
        }
    }

    const int gy = ty0 + py, gx = tx0 + pxl;
    size_t base = (((size_t)b * C_ + cg * 8 + csub * 2) * 128 + 2 * gy) * 128 + 2 * gx;
#pragma unroll
    for (int ch = 0; ch < 2; ch++) {
        *(ull*)(out + base)       = acc01[ch];   // (s00, s01)
        *(ull*)(out + base + 128) = acc23[ch];   // (s10, s11)
        base += (size_t)128 * 128;
    }
}

// ---------------------------------------------------------------------------
extern "C" void kernel_launch(void* const* d_in, const int* in_sizes, int n_in,
                              void* d_out, int out_size)
{
    const float* x       = (const float*)d_in[0];
    const float* w_comp  = (const float*)d_in[1];
    const float* bn_g    = (const float*)d_in[2];
    const float* bn_b    = (const float*)d_in[3];
    const float* bn_m    = (const float*)d_in[4];
    const float* bn_v    = (const float*)d_in[5];
    const float* w_enc   = (const float*)d_in[6];
    float* out = (float*)d_out;

    cudaFuncSetAttribute(k_reassemble, cudaFuncAttributeMaxDynamicSharedMemorySize,
                         RA_SMEM_BYTES);

    dim3 g1(16, 8, B_);
    k_compress<<<g1, 512>>>(x, w_comp, bn_g, bn_b, bn_m, bn_v);

    dim3 g2(16, 16, B_);
    k_encoder<<<g2, 256>>>(w_enc);

    k_combine<<<256, 256>>>();

    dim3 g3(64, 32, B_);
    k_reassemble<<<g3, 256, RA_SMEM_BYTES>>>(x, out);
}